// round 14
// baseline (speedup 1.0000x reference)
#include <cuda_runtime.h>
#include <cuda_fp16.h>
#include <cstdint>
#include <math.h>

static constexpr int B_ = 8, S_ = 2048, D_ = 1024, H_ = 1024;
static constexpr int M_ = B_ * S_;  // 16384

// Tiling: 128x128 CTA tile, BK=32, 128 threads (4 warps, warp tile 64x64).
static constexpr int BM = 128, BN = 128, BK = 32;
static constexpr int ROWB = 80;                    // 64 data bytes + 16 pad
static constexpr int PL = BM * ROWB;               // 10240 per plane
static constexpr int STG = 2 * PL;                 // 20480 per stage
static constexpr int NST = 3;
static constexpr int SMEM_BYTES = NST * STG;       // 61440 (3 CTAs/SM: 184KB)

static constexpr float SHIFT = 3.0f;               // exp(s - SHIFT), cancels in norm
static constexpr float LOG2E = 1.4426950408889634f;

// Device scratch (allocation-free rule: __device__ globals)
__device__ __half g_xh[(size_t)M_ * D_];
__device__ __half g_wh[3][(size_t)H_ * D_];
__device__ __half g_qkv[2][(size_t)M_ * H_];       // q, k planes
__device__ __half g_vth[(size_t)M_ * H_];          // V transposed [H][M]
__device__ __half g_ph[(size_t)B_ * S_ * S_];
__device__ float  g_rsum[M_];

// ---------------------------------------------------------------------------
// helpers
// ---------------------------------------------------------------------------
__device__ __forceinline__ uint32_t smem_u32(const void* p) {
    uint32_t a;
    asm("{ .reg .u64 t; cvta.to.shared.u64 t, %1; cvt.u32.u64 %0, t; }"
        : "=r"(a) : "l"(p));
    return a;
}

#define CP16(dst, src) \
    asm volatile("cp.async.cg.shared.global [%0], [%1], 16;" :: "r"(dst), "l"(src))
#define CP_COMMIT() asm volatile("cp.async.commit_group;" ::: "memory")
#define CP_WAIT1()  asm volatile("cp.async.wait_group 1;" ::: "memory")
#define CP_WAIT0()  asm volatile("cp.async.wait_group 0;" ::: "memory")

__device__ __forceinline__ void mma16(float* d, const uint32_t* a, const uint32_t* b) {
    asm volatile(
        "mma.sync.aligned.m16n8k16.row.col.f32.f16.f16.f32 "
        "{%0,%1,%2,%3},{%4,%5,%6,%7},{%8,%9},{%0,%1,%2,%3};"
        : "+f"(d[0]), "+f"(d[1]), "+f"(d[2]), "+f"(d[3])
        : "r"(a[0]), "r"(a[1]), "r"(a[2]), "r"(a[3]), "r"(b[0]), "r"(b[1]));
}

__device__ __forceinline__ void ldsm4(uint32_t* r, uint32_t addr) {
    asm volatile(
        "ldmatrix.sync.aligned.m8n8.x4.shared.b16 {%0,%1,%2,%3}, [%4];"
        : "=r"(r[0]), "=r"(r[1]), "=r"(r[2]), "=r"(r[3]) : "r"(addr));
}

// ---------------------------------------------------------------------------
// Per-stage compute: 2 k16 steps, warp tile 64x64, single-pass fp16.
// 8 LDSM feed 32 MMAs per k16 step (1.0 L1-wavefront per MMA).
// ---------------------------------------------------------------------------
__device__ __forceinline__ void compute_tile(
    uint32_t buf, float (&acc)[4][8][4], uint32_t aBase, uint32_t bBase)
{
#pragma unroll
    for (int ks = 0; ks < 2; ks++) {
        const uint32_t kb = ks * 32;
        uint32_t bh[4][4];
#pragma unroll
        for (int ntp = 0; ntp < 4; ntp++)
            ldsm4(bh[ntp], buf + PL + bBase + ntp * 16 * ROWB + kb);
#pragma unroll
        for (int mt = 0; mt < 4; mt++) {
            uint32_t af[4];
            ldsm4(af, buf + aBase + mt * 16 * ROWB + kb);
#pragma unroll
            for (int nt = 0; nt < 8; nt++) {
                const int ntp = nt >> 1, s = nt & 1;
                uint32_t b0[2] = {bh[ntp][s], bh[ntp][s + 2]};
                mma16(acc[mt][nt], af, b0);
            }
        }
    }
}

// ---------------------------------------------------------------------------
// NT GEMM on fp16 planes: C[m,n] = sum_k A[m,k]*B[n,k]
// MODE 0: fused QKV -> z=0/1 write q/k planes; z=2 writes V TRANSPOSED to vt
// MODE 2: scores    -> triangular grid; p~=exp(s*scale-SHIFT); atomic row sums
// MODE 3: PV        -> fp32 / rsum[row], Kend = m0+BM, largest-K-first order
// ---------------------------------------------------------------------------
template <int MODE>
__global__ __launch_bounds__(128, 3) void gemm_h(
    const __half* __restrict__ A, const __half* __restrict__ Bh,
    const float* __restrict__ bias0, const float* __restrict__ bias1,
    const float* __restrict__ bias2, void* __restrict__ C0,
    __half* __restrict__ vt_out, float* __restrict__ rsum,
    int K, int lda, int ldb, int ldc,
    long sAz, long sBz, long sCz, float scale)
{
    int m0, n0;
    if (MODE == 2) {
        // triangular decode: blockIdx.x in [0,136) -> (mt, nt), nt <= mt
        const int t = blockIdx.x;
        int mt = (int)((__fsqrt_rn(8.f * t + 1.f) - 1.f) * 0.5f);
        while ((mt + 1) * (mt + 2) / 2 <= t) mt++;
        while (mt * (mt + 1) / 2 > t) mt--;
        m0 = mt * BM;
        n0 = (t - mt * (mt + 1) / 2) * BN;
    } else if (MODE == 3) {
        m0 = ((int)gridDim.y - 1 - (int)blockIdx.y) * BM;  // largest K first
        n0 = blockIdx.x * BN;
    } else {
        m0 = blockIdx.y * BM;
        n0 = blockIdx.x * BN;
    }

    const int z = blockIdx.z;
    A  += (size_t)z * sAz;
    Bh += (size_t)z * sBz;

    extern __shared__ char smx[];
    const uint32_t smb = smem_u32(smx);

    const int tid  = threadIdx.x;      // 0..127
    const int lane = tid & 31;
    const int wid  = tid >> 5;         // 0..3
    const int wm   = wid >> 1;         // 0..1 (64 rows)
    const int wn   = wid & 1;          // 0..1 (64 cols)
    const int g    = lane >> 2;
    const int tg   = lane & 3;

    // ldmatrix lane addressing
    const uint32_t lq = lane & 15, lh = lane >> 4;
    const uint32_t aBase = (wm * 64 + lq) * ROWB + lh * 16;
    const uint32_t bBase = (wn * 64 + lq) * ROWB + lh * 16;

    const int Kend = (MODE == 3) ? (m0 + BM) : K;
    const int KT   = Kend / BK;

    // cp.async mapping: rows lr4 + 32j (j=0..3), 16B segment c16 of 64B row
    const int lr4 = tid >> 2;          // 0..31
    const int c16 = tid & 3;
    const __half* pA  = A  + (size_t)(m0 + lr4) * lda + c16 * 8;
    const __half* pBh = Bh + (size_t)(n0 + lr4) * ldb + c16 * 8;
    const size_t a32 = (size_t)32 * lda, b32 = (size_t)32 * ldb;
    const uint32_t dst0 = smb + lr4 * ROWB + c16 * 16;

    float acc[4][8][4];
#pragma unroll
    for (int i = 0; i < 4; i++)
#pragma unroll
        for (int j = 0; j < 8; j++)
#pragma unroll
            for (int e = 0; e < 4; e++) acc[i][j][e] = 0.f;

#define ISSUE(kt)                                                          \
    do {                                                                   \
        const uint32_t d = dst0 + ((kt) % NST) * STG;                      \
        const int koff = (kt) * BK;                                        \
        CP16(d,                   pA  + koff);                             \
        CP16(d + 32 * ROWB,       pA  + koff + a32);                       \
        CP16(d + 64 * ROWB,       pA  + koff + 2 * a32);                   \
        CP16(d + 96 * ROWB,       pA  + koff + 3 * a32);                   \
        CP16(d + PL,              pBh + koff);                             \
        CP16(d + PL + 32 * ROWB,  pBh + koff + b32);                       \
        CP16(d + PL + 64 * ROWB,  pBh + koff + 2 * b32);                   \
        CP16(d + PL + 96 * ROWB,  pBh + koff + 3 * b32);                   \
        CP_COMMIT();                                                       \
    } while (0)

    ISSUE(0);
    ISSUE(1);

    for (int kt = 0; kt < KT; kt++) {
        // stage kt resident: allow 1 outstanding except on the final chunk
        if (kt < KT - 1) { CP_WAIT1(); } else { CP_WAIT0(); }
        __syncthreads();     // all warps done with the buffer being rewritten
        if (kt + 2 < KT) ISSUE(kt + 2);
        compute_tile(smb + (kt % NST) * STG, acc, aBase, bBase);
    }
#undef ISSUE

    // ------------------------------ epilogue -------------------------------
    if (MODE == 0 && z == 2) {
        // V: write transposed. Stage tile into SMEM transposed, then
        // coalesced 16B stores along the M dimension of vt_out[H][M].
        __syncthreads();                 // mainloop reads done; reuse smx
        __half* T2 = (__half*)smx;       // [128 h-rows][136 halves (272B)]
#pragma unroll
        for (int mt = 0; mt < 4; mt++)
#pragma unroll
            for (int nt = 0; nt < 8; nt++) {
                const int lr = wm * 64 + mt * 16 + g;
                const int lc = wn * 64 + nt * 8 + tg * 2;
                const float2 b2 = *(const float2*)(bias2 + n0 + lc);
                float* c = acc[mt][nt];
                T2[(lc)     * 136 + lr]     = __float2half_rn(c[0] + b2.x);
                T2[(lc + 1) * 136 + lr]     = __float2half_rn(c[1] + b2.y);
                T2[(lc)     * 136 + lr + 8] = __float2half_rn(c[2] + b2.x);
                T2[(lc + 1) * 136 + lr + 8] = __float2half_rn(c[3] + b2.y);
            }
        __syncthreads();
#pragma unroll
        for (int rep = 0; rep < 16; rep++) {
            const int idx = rep * 128 + tid;
            const int hh = idx >> 4;      // 0..127 (H within tile)
            const int mc = idx & 15;      // 16B chunk along M
            uint4 v = *(const uint4*)((const char*)smx + hh * 272 + mc * 16);
            *(uint4*)(vt_out + (size_t)(n0 + hh) * M_ + m0 + mc * 8) = v;
        }
        return;
    }

#pragma unroll
    for (int mt = 0; mt < 4; mt++) {
        float s0 = 0.f, s1 = 0.f;        // MODE 2 row partial sums
#pragma unroll
        for (int nt = 0; nt < 8; nt++) {
            const int row = m0 + wm * 64 + mt * 16 + g;
            const int col = n0 + wn * 64 + nt * 8 + tg * 2;
            float* c = acc[mt][nt];
            if (MODE == 0) {
                __half* Ch = (__half*)C0 + (size_t)z * sCz;
                const float* bias = (z == 0) ? bias0 : bias1;
                const float2 b2 = *(const float2*)(bias + col);
                *(__half2*)(Ch + (size_t)row * ldc + col) =
                    __floats2half2_rn(c[0] + b2.x, c[1] + b2.y);
                *(__half2*)(Ch + (size_t)(row + 8) * ldc + col) =
                    __floats2half2_rn(c[2] + b2.x, c[3] + b2.y);
            } else if (MODE == 2) {
                __half* Ph = (__half*)C0 + (size_t)z * sCz;
                float e0 = (col     <= row    ) ? exp2f((c[0] * scale - SHIFT) * LOG2E) : 0.f;
                float e1 = (col + 1 <= row    ) ? exp2f((c[1] * scale - SHIFT) * LOG2E) : 0.f;
                float e2 = (col     <= row + 8) ? exp2f((c[2] * scale - SHIFT) * LOG2E) : 0.f;
                float e3 = (col + 1 <= row + 8) ? exp2f((c[3] * scale - SHIFT) * LOG2E) : 0.f;
                s0 += e0 + e1;
                s1 += e2 + e3;
                *(__half2*)(Ph + (size_t)row * ldc + col)       = __floats2half2_rn(e0, e1);
                *(__half2*)(Ph + (size_t)(row + 8) * ldc + col) = __floats2half2_rn(e2, e3);
            } else {
                float* C = (float*)C0 + (size_t)z * sCz;
                const float r0 = 1.f / rsum[z * S_ + row];
                const float r1 = 1.f / rsum[z * S_ + row + 8];
                *(float2*)(C + (size_t)row * ldc + col) =
                    make_float2(c[0] * r0, c[1] * r0);
                *(float2*)(C + (size_t)(row + 8) * ldc + col) =
                    make_float2(c[2] * r1, c[3] * r1);
            }
        }
        if (MODE == 2) {
            // reduce across the quad (tg lanes share the same rows)
            s0 += __shfl_xor_sync(0xffffffffu, s0, 1);
            s0 += __shfl_xor_sync(0xffffffffu, s0, 2);
            s1 += __shfl_xor_sync(0xffffffffu, s1, 1);
            s1 += __shfl_xor_sync(0xffffffffu, s1, 2);
            if (tg == 0) {
                const int row = m0 + wm * 64 + mt * 16 + g;
                atomicAdd(&rsum[z * S_ + row], s0);
                atomicAdd(&rsum[z * S_ + row + 8], s1);
            }
        }
    }
}

// ---------------------------------------------------------------------------
// fp32 -> fp16 conversion (single src)
// ---------------------------------------------------------------------------
__global__ __launch_bounds__(256) void cvt_h(
    const float* __restrict__ in, __half* __restrict__ out)
{
    const size_t i = ((size_t)blockIdx.x * 256 + threadIdx.x) * 4;
    float4 v = *(const float4*)(in + i);
    *(__half2*)(out + i)     = __floats2half2_rn(v.x, v.y);
    *(__half2*)(out + i + 2) = __floats2half2_rn(v.z, v.w);
}

// fp32 -> fp16 conversion for the 3 weight matrices (z-indexed)
__global__ __launch_bounds__(256) void cvt_w(
    const float* __restrict__ w0, const float* __restrict__ w1,
    const float* __restrict__ w2, __half* __restrict__ out)
{
    const int z = blockIdx.y;
    const float* in = (z == 0) ? w0 : ((z == 1) ? w1 : w2);
    const size_t i = ((size_t)blockIdx.x * 256 + threadIdx.x) * 4;
    float4 v = *(const float4*)(in + i);
    __half* o = out + (size_t)z * H_ * D_;
    *(__half2*)(o + i)     = __floats2half2_rn(v.x, v.y);
    *(__half2*)(o + i + 2) = __floats2half2_rn(v.z, v.w);
}

// ---------------------------------------------------------------------------
// Launch pipeline (graph-capturable)
// ---------------------------------------------------------------------------
extern "C" void kernel_launch(void* const* d_in, const int* in_sizes, int n_in,
                              void* d_out, int out_size)
{
    (void)in_sizes; (void)n_in; (void)out_size;
    const float* x  = (const float*)d_in[0];
    const float* Wq = (const float*)d_in[1];
    const float* bq = (const float*)d_in[2];
    const float* Wk = (const float*)d_in[3];
    const float* bk = (const float*)d_in[4];
    const float* Wv = (const float*)d_in[5];
    const float* bv = (const float*)d_in[6];
    float* out = (float*)d_out;

    __half *xh, *wh, *qkv, *vth, *ph;
    float* rsum;
    cudaGetSymbolAddress((void**)&xh,   g_xh);
    cudaGetSymbolAddress((void**)&wh,   g_wh);
    cudaGetSymbolAddress((void**)&qkv,  g_qkv);
    cudaGetSymbolAddress((void**)&vth,  g_vth);
    cudaGetSymbolAddress((void**)&ph,   g_ph);
    cudaGetSymbolAddress((void**)&rsum, g_rsum);

    const __half* qh = qkv;
    const __half* kh = qkv + (size_t)M_ * H_;

    cudaFuncSetAttribute(gemm_h<0>, cudaFuncAttributeMaxDynamicSharedMemorySize, SMEM_BYTES);
    cudaFuncSetAttribute(gemm_h<2>, cudaFuncAttributeMaxDynamicSharedMemorySize, SMEM_BYTES);
    cudaFuncSetAttribute(gemm_h<3>, cudaFuncAttributeMaxDynamicSharedMemorySize, SMEM_BYTES);

    const dim3 blk(128);
    const dim3 blk256(256);

    // 0) convert operands to fp16; zero the row-sum accumulator
    cvt_h<<<M_ * D_ / 1024, blk256>>>(x, xh);
    cvt_w<<<dim3(H_ * D_ / 1024, 3), blk256>>>(Wq, Wk, Wv, wh);
    cudaMemsetAsync(rsum, 0, M_ * sizeof(float));

    // 1) fused QKV projection: z=0/1 -> q/k planes; z=2 -> vth (transposed)
    const dim3 gq(H_ / BN, M_ / BM, 3);  // 3072 CTAs
    gemm_h<0><<<gq, blk, SMEM_BYTES>>>(xh, wh, bq, bk, bv, qkv, vth, nullptr,
                                       D_, D_, D_, H_,
                                       0, (long)H_ * D_, (long)M_ * H_, 1.f);

    // 2) Scores -> p~ = exp(s/32 - SHIFT), fp16, causal; packed triangular
    //    grid; epilogue accumulates row sums into rsum via atomics.
    const dim3 gs(136, 1, B_);  // 1088 CTAs, all live
    gemm_h<2><<<gs, blk, SMEM_BYTES>>>(qh, kh, nullptr, nullptr, nullptr, ph,
                                       nullptr, rsum,
                                       H_, H_, H_, S_,
                                       (long)S_ * H_, (long)S_ * H_, (long)S_ * S_,
                                       0.03125f);

    // 3) O = (p~ @ V) / rsum  (B = V^T, causal k-limit, largest-K tiles first)
    const dim3 gp(H_ / BN, S_ / BM, B_);
    gemm_h<3><<<gp, blk, SMEM_BYTES>>>(ph, vth, nullptr, nullptr, nullptr, out,
                                       nullptr, rsum,
                                       S_, S_, M_, H_,
                                       (long)S_ * S_, (long)S_, (long)S_ * H_, 1.f);
}

// round 15
// speedup vs baseline: 1.0124x; 1.0124x over previous
#include <cuda_runtime.h>
#include <cuda_fp16.h>
#include <cstdint>
#include <math.h>

static constexpr int B_ = 8, S_ = 2048, D_ = 1024, H_ = 1024;
static constexpr int M_ = B_ * S_;  // 16384

// Tiling: 128x128 CTA tile, BK=32. fp16 planes in SMEM: A_h, B_h. (R12 config)
static constexpr int BM = 128, BN = 128, BK = 32;
static constexpr int ROWB = 80;                    // 64 data bytes + 16 pad
static constexpr int PL = BM * ROWB;               // 10240 per plane
static constexpr int STG = 2 * PL;                 // 20480 per stage
static constexpr int NST = 4;
static constexpr int SMEM_BYTES = NST * STG;       // 81920

static constexpr float SHIFT = 3.0f;               // exp(s - SHIFT), cancels in norm
static constexpr float LOG2E = 1.4426950408889634f;

// Device scratch (allocation-free rule: __device__ globals)
__device__ __half g_xh[(size_t)M_ * D_];
__device__ __half g_wh[3][(size_t)H_ * D_];
__device__ __half g_qkv[2][(size_t)M_ * H_];       // q, k planes
__device__ __half g_vth[(size_t)M_ * H_];          // V transposed [H][M]
__device__ __half g_ph[(size_t)B_ * S_ * S_];
__device__ float  g_rsum[M_];

// Streams/events for graph-captured fork-join (created at program load;
// kernel_launch itself stays guard-free and deterministic).
static cudaStream_t g_s1;
static cudaEvent_t  g_evQK, g_evV, g_evSA, g_evPA;
static const int g_init_once = []() {
    cudaStreamCreateWithFlags(&g_s1, cudaStreamNonBlocking);
    cudaEventCreateWithFlags(&g_evQK, cudaEventDisableTiming);
    cudaEventCreateWithFlags(&g_evV,  cudaEventDisableTiming);
    cudaEventCreateWithFlags(&g_evSA, cudaEventDisableTiming);
    cudaEventCreateWithFlags(&g_evPA, cudaEventDisableTiming);
    return 0;
}();

// ---------------------------------------------------------------------------
// helpers
// ---------------------------------------------------------------------------
__device__ __forceinline__ uint32_t smem_u32(const void* p) {
    uint32_t a;
    asm("{ .reg .u64 t; cvta.to.shared.u64 t, %1; cvt.u32.u64 %0, t; }"
        : "=r"(a) : "l"(p));
    return a;
}

#define CP16(dst, src) \
    asm volatile("cp.async.cg.shared.global [%0], [%1], 16;" :: "r"(dst), "l"(src))
#define CP_COMMIT() asm volatile("cp.async.commit_group;" ::: "memory")
#define CP_WAIT2()  asm volatile("cp.async.wait_group 2;" ::: "memory")
#define CP_WAIT1()  asm volatile("cp.async.wait_group 1;" ::: "memory")
#define CP_WAIT0()  asm volatile("cp.async.wait_group 0;" ::: "memory")

__device__ __forceinline__ void mma16(float* d, const uint32_t* a, const uint32_t* b) {
    asm volatile(
        "mma.sync.aligned.m16n8k16.row.col.f32.f16.f16.f32 "
        "{%0,%1,%2,%3},{%4,%5,%6,%7},{%8,%9},{%0,%1,%2,%3};"
        : "+f"(d[0]), "+f"(d[1]), "+f"(d[2]), "+f"(d[3])
        : "r"(a[0]), "r"(a[1]), "r"(a[2]), "r"(a[3]), "r"(b[0]), "r"(b[1]));
}

__device__ __forceinline__ void ldsm4(uint32_t* r, uint32_t addr) {
    asm volatile(
        "ldmatrix.sync.aligned.m8n8.x4.shared.b16 {%0,%1,%2,%3}, [%4];"
        : "=r"(r[0]), "=r"(r[1]), "=r"(r[2]), "=r"(r[3]) : "r"(addr));
}

// ---------------------------------------------------------------------------
// Per-stage compute: 2 k16 steps, warp tile 64x32, single-pass fp16.
// ---------------------------------------------------------------------------
__device__ __forceinline__ void compute_tile(
    uint32_t buf, float (&acc)[4][4][4], uint32_t aBase, uint32_t bBase)
{
#pragma unroll
    for (int ks = 0; ks < 2; ks++) {
        const uint32_t kb = ks * 32;
        uint32_t bh[2][4];
#pragma unroll
        for (int ntp = 0; ntp < 2; ntp++)
            ldsm4(bh[ntp], buf + PL + bBase + ntp * 16 * ROWB + kb);
#pragma unroll
        for (int mt = 0; mt < 4; mt++) {
            uint32_t af[4];
            ldsm4(af, buf + aBase + mt * 16 * ROWB + kb);
#pragma unroll
            for (int nt = 0; nt < 4; nt++) {
                const int ntp = nt >> 1, s = nt & 1;
                uint32_t b0[2] = {bh[ntp][s], bh[ntp][s + 2]};
                mma16(acc[mt][nt], af, b0);
            }
        }
    }
}

// ---------------------------------------------------------------------------
// NT GEMM on fp16 planes: C[m,n] = sum_k A[m,k]*B[n,k]
// MODE 0: QK proj  -> z=0/1 select Wq/Wk plane + bias; write q/k planes
// MODE 1: V proj   -> writes V TRANSPOSED to vt_out
// MODE 2: scores   -> triangular grid; p~=exp(s*scale-SHIFT); atomic row sums
// MODE 3: PV       -> fp32 / rsum[row], Kend = m0+BM, largest-K-first order
// ---------------------------------------------------------------------------
template <int MODE>
__global__ __launch_bounds__(256, 2) void gemm_h(
    const __half* __restrict__ A, const __half* __restrict__ Bh,
    const float* __restrict__ bias0, const float* __restrict__ bias1,
    void* __restrict__ C0, __half* __restrict__ vt_out,
    float* __restrict__ rsum,
    int K, int lda, int ldb, int ldc,
    long sAz, long sBz, long sCz, float scale)
{
    int m0, n0;
    if (MODE == 2) {
        // triangular decode: blockIdx.x in [0,136) -> (mt, nt), nt <= mt
        const int t = blockIdx.x;
        int mt = (int)((__fsqrt_rn(8.f * t + 1.f) - 1.f) * 0.5f);
        while ((mt + 1) * (mt + 2) / 2 <= t) mt++;
        while (mt * (mt + 1) / 2 > t) mt--;
        m0 = mt * BM;
        n0 = (t - mt * (mt + 1) / 2) * BN;
    } else if (MODE == 3) {
        m0 = ((int)gridDim.y - 1 - (int)blockIdx.y) * BM;  // largest K first
        n0 = blockIdx.x * BN;
    } else {
        m0 = blockIdx.y * BM;
        n0 = blockIdx.x * BN;
    }

    const int z = blockIdx.z;
    A  += (size_t)z * sAz;
    Bh += (size_t)z * sBz;

    extern __shared__ char smx[];
    const uint32_t smb = smem_u32(smx);

    const int tid  = threadIdx.x;
    const int lane = tid & 31;
    const int wid  = tid >> 5;
    const int wm   = wid >> 2;   // 0..1 (64 rows)
    const int wn   = wid & 3;    // 0..3 (32 cols)
    const int g    = lane >> 2;
    const int tg   = lane & 3;

    // ldmatrix lane addressing
    const uint32_t lq = lane & 15, lh = lane >> 4;
    const uint32_t aBase = (wm * 64 + lq) * ROWB + lh * 16;
    const uint32_t bBase = (wn * 32 + lq) * ROWB + lh * 16;

    const int Kend = (MODE == 3) ? (m0 + BM) : K;
    const int KT   = Kend / BK;

    // cp.async mapping: rows lr4 and lr4+64, 16B segment c16 of the 64B row
    const int lr4 = tid >> 2;
    const int c16 = tid & 3;
    const __half* pA  = A  + (size_t)(m0 + lr4) * lda + c16 * 8;
    const __half* pBh = Bh + (size_t)(n0 + lr4) * ldb + c16 * 8;
    const size_t a64 = (size_t)64 * lda, b64 = (size_t)64 * ldb;
    const uint32_t dst0 = smb + lr4 * ROWB + c16 * 16;

    float acc[4][4][4];
#pragma unroll
    for (int i = 0; i < 4; i++)
#pragma unroll
        for (int j = 0; j < 4; j++)
#pragma unroll
            for (int e = 0; e < 4; e++) acc[i][j][e] = 0.f;

#define ISSUE(kt)                                                          \
    do {                                                                   \
        const uint32_t d = dst0 + ((kt) % NST) * STG;                      \
        const int koff = (kt) * BK;                                        \
        CP16(d,                  pA  + koff);                              \
        CP16(d + 64 * ROWB,      pA  + koff + a64);                        \
        CP16(d + PL,             pBh + koff);                              \
        CP16(d + PL + 64 * ROWB, pBh + koff + b64);                        \
        CP_COMMIT();                                                       \
    } while (0)

    ISSUE(0);
    ISSUE(1);
    ISSUE(2);

    for (int kt = 0; kt < KT; kt++) {
        // stage kt resident (race-safe tail: 2/1/0 outstanding groups)
        if (kt < KT - 2)       { CP_WAIT2(); }
        else if (kt == KT - 2) { CP_WAIT1(); }
        else                   { CP_WAIT0(); }
        __syncthreads();     // all warps done with the buffer being rewritten
        if (kt + 3 < KT) ISSUE(kt + 3);
        compute_tile(smb + (kt % NST) * STG, acc, aBase, bBase);
    }
#undef ISSUE

    // ------------------------------ epilogue -------------------------------
    if (MODE == 1) {
        // V: write transposed. Stage tile into SMEM transposed, then
        // coalesced 16B stores along the M dimension of vt_out[H][M].
        __syncthreads();                 // mainloop reads done; reuse smx
        __half* T2 = (__half*)smx;       // [128 h-rows][136 halves (272B)]
#pragma unroll
        for (int mt = 0; mt < 4; mt++)
#pragma unroll
            for (int nt = 0; nt < 4; nt++) {
                const int lr = wm * 64 + mt * 16 + g;
                const int lc = wn * 32 + nt * 8 + tg * 2;
                const float2 b2 = *(const float2*)(bias0 + n0 + lc);
                float* c = acc[mt][nt];
                T2[(lc)     * 136 + lr]     = __float2half_rn(c[0] + b2.x);
                T2[(lc + 1) * 136 + lr]     = __float2half_rn(c[1] + b2.y);
                T2[(lc)     * 136 + lr + 8] = __float2half_rn(c[2] + b2.x);
                T2[(lc + 1) * 136 + lr + 8] = __float2half_rn(c[3] + b2.y);
            }
        __syncthreads();
#pragma unroll
        for (int rep = 0; rep < 8; rep++) {
            const int idx = rep * 256 + tid;
            const int hh = idx >> 4;      // 0..127 (H within tile)
            const int mc = idx & 15;      // 16B chunk along M
            uint4 v = *(const uint4*)((const char*)smx + hh * 272 + mc * 16);
            *(uint4*)(vt_out + (size_t)(n0 + hh) * M_ + m0 + mc * 8) = v;
        }
        return;
    }

#pragma unroll
    for (int mt = 0; mt < 4; mt++) {
        float s0 = 0.f, s1 = 0.f;        // MODE 2 row partial sums
#pragma unroll
        for (int nt = 0; nt < 4; nt++) {
            const int row = m0 + wm * 64 + mt * 16 + g;
            const int col = n0 + wn * 32 + nt * 8 + tg * 2;
            float* c = acc[mt][nt];
            if (MODE == 0) {
                __half* Ch = (__half*)C0 + (size_t)z * sCz;
                const float* bias = (z == 0) ? bias0 : bias1;
                const float2 b2 = *(const float2*)(bias + col);
                *(__half2*)(Ch + (size_t)row * ldc + col) =
                    __floats2half2_rn(c[0] + b2.x, c[1] + b2.y);
                *(__half2*)(Ch + (size_t)(row + 8) * ldc + col) =
                    __floats2half2_rn(c[2] + b2.x, c[3] + b2.y);
            } else if (MODE == 2) {
                __half* Ph = (__half*)C0 + (size_t)z * sCz;
                float e0 = (col     <= row    ) ? exp2f((c[0] * scale - SHIFT) * LOG2E) : 0.f;
                float e1 = (col + 1 <= row    ) ? exp2f((c[1] * scale - SHIFT) * LOG2E) : 0.f;
                float e2 = (col     <= row + 8) ? exp2f((c[2] * scale - SHIFT) * LOG2E) : 0.f;
                float e3 = (col + 1 <= row + 8) ? exp2f((c[3] * scale - SHIFT) * LOG2E) : 0.f;
                s0 += e0 + e1;
                s1 += e2 + e3;
                *(__half2*)(Ph + (size_t)row * ldc + col)       = __floats2half2_rn(e0, e1);
                *(__half2*)(Ph + (size_t)(row + 8) * ldc + col) = __floats2half2_rn(e2, e3);
            } else {
                float* C = (float*)C0 + (size_t)z * sCz;
                const float r0 = 1.f / rsum[z * S_ + row];
                const float r1 = 1.f / rsum[z * S_ + row + 8];
                *(float2*)(C + (size_t)row * ldc + col) =
                    make_float2(c[0] * r0, c[1] * r0);
                *(float2*)(C + (size_t)(row + 8) * ldc + col) =
                    make_float2(c[2] * r1, c[3] * r1);
            }
        }
        if (MODE == 2) {
            // reduce across the quad (tg lanes share the same rows)
            s0 += __shfl_xor_sync(0xffffffffu, s0, 1);
            s0 += __shfl_xor_sync(0xffffffffu, s0, 2);
            s1 += __shfl_xor_sync(0xffffffffu, s1, 1);
            s1 += __shfl_xor_sync(0xffffffffu, s1, 2);
            if (tg == 0) {
                const int row = m0 + wm * 64 + mt * 16 + g;
                atomicAdd(&rsum[z * S_ + row], s0);
                atomicAdd(&rsum[z * S_ + row + 8], s1);
            }
        }
    }
}

// ---------------------------------------------------------------------------
// fp32 -> fp16 conversion (single src)
// ---------------------------------------------------------------------------
__global__ __launch_bounds__(256) void cvt_h(
    const float* __restrict__ in, __half* __restrict__ out)
{
    const size_t i = ((size_t)blockIdx.x * 256 + threadIdx.x) * 4;
    float4 v = *(const float4*)(in + i);
    *(__half2*)(out + i)     = __floats2half2_rn(v.x, v.y);
    *(__half2*)(out + i + 2) = __floats2half2_rn(v.z, v.w);
}

// fp32 -> fp16 conversion for the 3 weight matrices (z-indexed)
__global__ __launch_bounds__(256) void cvt_w(
    const float* __restrict__ w0, const float* __restrict__ w1,
    const float* __restrict__ w2, __half* __restrict__ out)
{
    const int z = blockIdx.y;
    const float* in = (z == 0) ? w0 : ((z == 1) ? w1 : w2);
    const size_t i = ((size_t)blockIdx.x * 256 + threadIdx.x) * 4;
    float4 v = *(const float4*)(in + i);
    __half* o = out + (size_t)z * H_ * D_;
    *(__half2*)(o + i)     = __floats2half2_rn(v.x, v.y);
    *(__half2*)(o + i + 2) = __floats2half2_rn(v.z, v.w);
}

// ---------------------------------------------------------------------------
// Launch pipeline (graph-capturable, fork-join on two streams)
// ---------------------------------------------------------------------------
extern "C" void kernel_launch(void* const* d_in, const int* in_sizes, int n_in,
                              void* d_out, int out_size)
{
    (void)in_sizes; (void)n_in; (void)out_size;
    const float* x  = (const float*)d_in[0];
    const float* Wq = (const float*)d_in[1];
    const float* bq = (const float*)d_in[2];
    const float* Wk = (const float*)d_in[3];
    const float* bk = (const float*)d_in[4];
    const float* Wv = (const float*)d_in[5];
    const float* bv = (const float*)d_in[6];
    float* out = (float*)d_out;

    __half *xh, *wh, *qkv, *vth, *ph;
    float* rsum;
    cudaGetSymbolAddress((void**)&xh,   g_xh);
    cudaGetSymbolAddress((void**)&wh,   g_wh);
    cudaGetSymbolAddress((void**)&qkv,  g_qkv);
    cudaGetSymbolAddress((void**)&vth,  g_vth);
    cudaGetSymbolAddress((void**)&ph,   g_ph);
    cudaGetSymbolAddress((void**)&rsum, g_rsum);

    const __half* qh = qkv;
    const __half* kh = qkv + (size_t)M_ * H_;

    cudaFuncSetAttribute(gemm_h<0>, cudaFuncAttributeMaxDynamicSharedMemorySize, SMEM_BYTES);
    cudaFuncSetAttribute(gemm_h<1>, cudaFuncAttributeMaxDynamicSharedMemorySize, SMEM_BYTES);
    cudaFuncSetAttribute(gemm_h<2>, cudaFuncAttributeMaxDynamicSharedMemorySize, SMEM_BYTES);
    cudaFuncSetAttribute(gemm_h<3>, cudaFuncAttributeMaxDynamicSharedMemorySize, SMEM_BYTES);

    const dim3 blk(256);
    const long sQK = (long)S_ * H_;       // q/k batch stride
    const long sP  = (long)S_ * S_;       // p batch stride

    // 0) convert operands to fp16; zero the row-sum accumulator (main stream)
    cvt_h<<<M_ * D_ / 1024, blk>>>(x, xh);
    cvt_w<<<dim3(H_ * D_ / 1024, 3), blk>>>(Wq, Wk, Wv, wh);
    cudaMemsetAsync(rsum, 0, M_ * sizeof(float));

    // 1) QK projection (z=0/1 -> q/k planes), main stream
    const dim3 gqk(H_ / BN, M_ / BM, 2);
    gemm_h<0><<<gqk, blk, SMEM_BYTES>>>(xh, wh, bq, bk, qkv, nullptr, nullptr,
                                        D_, D_, D_, H_,
                                        0, (long)H_ * D_, (long)M_ * H_, 1.f);
    cudaEventRecord(g_evQK, 0);

    // 1b) V projection -> vth (transposed), side stream; overlaps scoresA
    cudaStreamWaitEvent(g_s1, g_evQK, 0);
    const dim3 gv(H_ / BN, M_ / BM, 1);
    gemm_h<1><<<gv, blk, SMEM_BYTES, g_s1>>>(xh, wh + 2 * (size_t)H_ * D_, bv,
                                             nullptr, nullptr, vth, nullptr,
                                             D_, D_, D_, H_, 0, 0, 0, 1.f);
    cudaEventRecord(g_evV, g_s1);

    // 2a) scoresA: batches 0..3 (main stream)
    const dim3 gs(136, 1, 4);
    gemm_h<2><<<gs, blk, SMEM_BYTES>>>(qh, kh, nullptr, nullptr, ph, nullptr,
                                       rsum, H_, H_, H_, S_,
                                       sQK, sQK, sP, 0.03125f);
    cudaEventRecord(g_evSA, 0);

    // 3a) PVA: batches 0..3 on side stream (after V, after scoresA)
    cudaStreamWaitEvent(g_s1, g_evSA, 0);
    const dim3 gp(H_ / BN, S_ / BM, 4);
    gemm_h<3><<<gp, blk, SMEM_BYTES, g_s1>>>(ph, vth, nullptr, nullptr, out,
                                             nullptr, rsum,
                                             S_, S_, M_, H_,
                                             sP, (long)S_, (long)S_ * H_, 1.f);
    cudaEventRecord(g_evPA, g_s1);

    // 2b) scoresB: batches 4..7 (main stream, overlaps PVA)
    gemm_h<2><<<gs, blk, SMEM_BYTES>>>(qh + 4 * (size_t)sQK, kh + 4 * (size_t)sQK,
                                       nullptr, nullptr, ph + 4 * (size_t)sP,
                                       nullptr, rsum + 4 * S_,
                                       H_, H_, H_, S_,
                                       sQK, sQK, sP, 0.03125f);

    // 3b) PVB: batches 4..7 (main stream; needs V)
    cudaStreamWaitEvent(0, g_evV, 0);
    gemm_h<3><<<gp, blk, SMEM_BYTES>>>(ph + 4 * (size_t)sP, vth + 4 * (size_t)S_,
                                       nullptr, nullptr, out + 4 * (size_t)S_ * H_,
                                       nullptr, rsum + 4 * S_,
                                       S_, S_, M_, H_,
                                       sP, (long)S_, (long)S_ * H_, 1.f);

    // join side stream back into the main stream
    cudaStreamWaitEvent(0, g_evPA, 0);
}

// round 16
// speedup vs baseline: 1.0763x; 1.0631x over previous
#include <cuda_runtime.h>
#include <cuda_fp16.h>
#include <cstdint>
#include <math.h>

static constexpr int B_ = 8, S_ = 2048, D_ = 1024, H_ = 1024;
static constexpr int M_ = B_ * S_;  // 16384

// Tiling: 128x128 CTA tile, BK=32. fp16 planes in SMEM: A_h, B_h. (R12 config)
static constexpr int BM = 128, BN = 128, BK = 32;
static constexpr int ROWB = 80;                    // 64 data bytes + 16 pad
static constexpr int PL = BM * ROWB;               // 10240 per plane
static constexpr int STG = 2 * PL;                 // 20480 per stage
static constexpr int NST = 4;
static constexpr int SMEM_BYTES = NST * STG;       // 81920

static constexpr float SHIFT = 3.0f;               // exp(s - SHIFT), cancels in norm
static constexpr float LOG2E = 1.4426950408889634f;

// Device scratch (allocation-free rule: __device__ globals)
__device__ __half g_xh[(size_t)M_ * D_];
__device__ __half g_wh[3][(size_t)H_ * D_];
__device__ __half g_qkv[2][(size_t)M_ * H_];       // q, k planes
__device__ __half g_vth[(size_t)M_ * H_];          // V transposed [H][M]
__device__ __half g_ph[(size_t)B_ * S_ * S_];
__device__ float  g_rsum[M_];

// Stream/events for the two batch-half pipelines (created at program load;
// kernel_launch itself stays guard-free and deterministic).
static cudaStream_t g_s1;
static cudaEvent_t  g_evCVT, g_evB;
static const int g_init_once = []() {
    cudaStreamCreateWithFlags(&g_s1, cudaStreamNonBlocking);
    cudaEventCreateWithFlags(&g_evCVT, cudaEventDisableTiming);
    cudaEventCreateWithFlags(&g_evB,   cudaEventDisableTiming);
    return 0;
}();

// ---------------------------------------------------------------------------
// helpers
// ---------------------------------------------------------------------------
__device__ __forceinline__ uint32_t smem_u32(const void* p) {
    uint32_t a;
    asm("{ .reg .u64 t; cvta.to.shared.u64 t, %1; cvt.u32.u64 %0, t; }"
        : "=r"(a) : "l"(p));
    return a;
}

#define CP16(dst, src) \
    asm volatile("cp.async.cg.shared.global [%0], [%1], 16;" :: "r"(dst), "l"(src))
#define CP_COMMIT() asm volatile("cp.async.commit_group;" ::: "memory")
#define CP_WAIT2()  asm volatile("cp.async.wait_group 2;" ::: "memory")
#define CP_WAIT1()  asm volatile("cp.async.wait_group 1;" ::: "memory")
#define CP_WAIT0()  asm volatile("cp.async.wait_group 0;" ::: "memory")

__device__ __forceinline__ void mma16(float* d, const uint32_t* a, const uint32_t* b) {
    asm volatile(
        "mma.sync.aligned.m16n8k16.row.col.f32.f16.f16.f32 "
        "{%0,%1,%2,%3},{%4,%5,%6,%7},{%8,%9},{%0,%1,%2,%3};"
        : "+f"(d[0]), "+f"(d[1]), "+f"(d[2]), "+f"(d[3])
        : "r"(a[0]), "r"(a[1]), "r"(a[2]), "r"(a[3]), "r"(b[0]), "r"(b[1]));
}

__device__ __forceinline__ void ldsm4(uint32_t* r, uint32_t addr) {
    asm volatile(
        "ldmatrix.sync.aligned.m8n8.x4.shared.b16 {%0,%1,%2,%3}, [%4];"
        : "=r"(r[0]), "=r"(r[1]), "=r"(r[2]), "=r"(r[3]) : "r"(addr));
}

// ---------------------------------------------------------------------------
// Per-stage compute: 2 k16 steps, warp tile 64x32, single-pass fp16.
// ---------------------------------------------------------------------------
__device__ __forceinline__ void compute_tile(
    uint32_t buf, float (&acc)[4][4][4], uint32_t aBase, uint32_t bBase)
{
#pragma unroll
    for (int ks = 0; ks < 2; ks++) {
        const uint32_t kb = ks * 32;
        uint32_t bh[2][4];
#pragma unroll
        for (int ntp = 0; ntp < 2; ntp++)
            ldsm4(bh[ntp], buf + PL + bBase + ntp * 16 * ROWB + kb);
#pragma unroll
        for (int mt = 0; mt < 4; mt++) {
            uint32_t af[4];
            ldsm4(af, buf + aBase + mt * 16 * ROWB + kb);
#pragma unroll
            for (int nt = 0; nt < 4; nt++) {
                const int ntp = nt >> 1, s = nt & 1;
                uint32_t b0[2] = {bh[ntp][s], bh[ntp][s + 2]};
                mma16(acc[mt][nt], af, b0);
            }
        }
    }
}

// ---------------------------------------------------------------------------
// NT GEMM on fp16 planes: C[m,n] = sum_k A[m,k]*B[n,k]   (R12 kernel, verbatim)
// MODE 0: fused QKV -> z=0/1 write q/k planes; z=2 writes V TRANSPOSED to vt
// MODE 2: scores    -> triangular grid; p~=exp(s*scale-SHIFT); atomic row sums
// MODE 3: PV        -> fp32 / rsum[row], Kend = m0+BM, largest-K-first order
// ---------------------------------------------------------------------------
template <int MODE>
__global__ __launch_bounds__(256, 2) void gemm_h(
    const __half* __restrict__ A, const __half* __restrict__ Bh,
    const float* __restrict__ bias0, const float* __restrict__ bias1,
    const float* __restrict__ bias2, void* __restrict__ C0,
    __half* __restrict__ vt_out, float* __restrict__ rsum,
    int K, int lda, int ldb, int ldc,
    long sAz, long sBz, long sCz, float scale)
{
    int m0, n0;
    if (MODE == 2) {
        // triangular decode: blockIdx.x in [0,136) -> (mt, nt), nt <= mt
        const int t = blockIdx.x;
        int mt = (int)((__fsqrt_rn(8.f * t + 1.f) - 1.f) * 0.5f);
        while ((mt + 1) * (mt + 2) / 2 <= t) mt++;
        while (mt * (mt + 1) / 2 > t) mt--;
        m0 = mt * BM;
        n0 = (t - mt * (mt + 1) / 2) * BN;
    } else if (MODE == 3) {
        m0 = ((int)gridDim.y - 1 - (int)blockIdx.y) * BM;  // largest K first
        n0 = blockIdx.x * BN;
    } else {
        m0 = blockIdx.y * BM;
        n0 = blockIdx.x * BN;
    }

    const int z = blockIdx.z;
    A  += (size_t)z * sAz;
    Bh += (size_t)z * sBz;

    extern __shared__ char smx[];
    const uint32_t smb = smem_u32(smx);

    const int tid  = threadIdx.x;
    const int lane = tid & 31;
    const int wid  = tid >> 5;
    const int wm   = wid >> 2;   // 0..1 (64 rows)
    const int wn   = wid & 3;    // 0..3 (32 cols)
    const int g    = lane >> 2;
    const int tg   = lane & 3;

    // ldmatrix lane addressing
    const uint32_t lq = lane & 15, lh = lane >> 4;
    const uint32_t aBase = (wm * 64 + lq) * ROWB + lh * 16;
    const uint32_t bBase = (wn * 32 + lq) * ROWB + lh * 16;

    const int Kend = (MODE == 3) ? (m0 + BM) : K;
    const int KT   = Kend / BK;

    // cp.async mapping: rows lr4 and lr4+64, 16B segment c16 of the 64B row
    const int lr4 = tid >> 2;
    const int c16 = tid & 3;
    const __half* pA  = A  + (size_t)(m0 + lr4) * lda + c16 * 8;
    const __half* pBh = Bh + (size_t)(n0 + lr4) * ldb + c16 * 8;
    const size_t a64 = (size_t)64 * lda, b64 = (size_t)64 * ldb;
    const uint32_t dst0 = smb + lr4 * ROWB + c16 * 16;

    float acc[4][4][4];
#pragma unroll
    for (int i = 0; i < 4; i++)
#pragma unroll
        for (int j = 0; j < 4; j++)
#pragma unroll
            for (int e = 0; e < 4; e++) acc[i][j][e] = 0.f;

#define ISSUE(kt)                                                          \
    do {                                                                   \
        const uint32_t d = dst0 + ((kt) % NST) * STG;                      \
        const int koff = (kt) * BK;                                        \
        CP16(d,                  pA  + koff);                              \
        CP16(d + 64 * ROWB,      pA  + koff + a64);                        \
        CP16(d + PL,             pBh + koff);                              \
        CP16(d + PL + 64 * ROWB, pBh + koff + b64);                        \
        CP_COMMIT();                                                       \
    } while (0)

    ISSUE(0);
    ISSUE(1);
    ISSUE(2);

    for (int kt = 0; kt < KT; kt++) {
        // stage kt resident (race-safe tail: 2/1/0 outstanding groups)
        if (kt < KT - 2)       { CP_WAIT2(); }
        else if (kt == KT - 2) { CP_WAIT1(); }
        else                   { CP_WAIT0(); }
        __syncthreads();     // all warps done with the buffer being rewritten
        if (kt + 3 < KT) ISSUE(kt + 3);
        compute_tile(smb + (kt % NST) * STG, acc, aBase, bBase);
    }
#undef ISSUE

    // ------------------------------ epilogue -------------------------------
    if (MODE == 0 && z == 2) {
        // V: write transposed. Stage tile into SMEM transposed, then
        // coalesced 16B stores along the M dimension of vt_out[H][M].
        __syncthreads();                 // mainloop reads done; reuse smx
        __half* T2 = (__half*)smx;       // [128 h-rows][136 halves (272B)]
#pragma unroll
        for (int mt = 0; mt < 4; mt++)
#pragma unroll
            for (int nt = 0; nt < 4; nt++) {
                const int lr = wm * 64 + mt * 16 + g;
                const int lc = wn * 32 + nt * 8 + tg * 2;
                const float2 b2 = *(const float2*)(bias2 + n0 + lc);
                float* c = acc[mt][nt];
                T2[(lc)     * 136 + lr]     = __float2half_rn(c[0] + b2.x);
                T2[(lc + 1) * 136 + lr]     = __float2half_rn(c[1] + b2.y);
                T2[(lc)     * 136 + lr + 8] = __float2half_rn(c[2] + b2.x);
                T2[(lc + 1) * 136 + lr + 8] = __float2half_rn(c[3] + b2.y);
            }
        __syncthreads();
#pragma unroll
        for (int rep = 0; rep < 8; rep++) {
            const int idx = rep * 256 + tid;
            const int hh = idx >> 4;      // 0..127 (H within tile)
            const int mc = idx & 15;      // 16B chunk along M
            uint4 v = *(const uint4*)((const char*)smx + hh * 272 + mc * 16);
            *(uint4*)(vt_out + (size_t)(n0 + hh) * M_ + m0 + mc * 8) = v;
        }
        return;
    }

#pragma unroll
    for (int mt = 0; mt < 4; mt++) {
        float s0 = 0.f, s1 = 0.f;        // MODE 2 row partial sums
#pragma unroll
        for (int nt = 0; nt < 4; nt++) {
            const int row = m0 + wm * 64 + mt * 16 + g;
            const int col = n0 + wn * 32 + nt * 8 + tg * 2;
            float* c = acc[mt][nt];
            if (MODE == 0) {
                __half* Ch = (__half*)C0 + (size_t)z * sCz;
                const float* bias = (z == 0) ? bias0 : bias1;
                const float2 b2 = *(const float2*)(bias + col);
                *(__half2*)(Ch + (size_t)row * ldc + col) =
                    __floats2half2_rn(c[0] + b2.x, c[1] + b2.y);
                *(__half2*)(Ch + (size_t)(row + 8) * ldc + col) =
                    __floats2half2_rn(c[2] + b2.x, c[3] + b2.y);
            } else if (MODE == 2) {
                __half* Ph = (__half*)C0 + (size_t)z * sCz;
                float e0 = (col     <= row    ) ? exp2f((c[0] * scale - SHIFT) * LOG2E) : 0.f;
                float e1 = (col + 1 <= row    ) ? exp2f((c[1] * scale - SHIFT) * LOG2E) : 0.f;
                float e2 = (col     <= row + 8) ? exp2f((c[2] * scale - SHIFT) * LOG2E) : 0.f;
                float e3 = (col + 1 <= row + 8) ? exp2f((c[3] * scale - SHIFT) * LOG2E) : 0.f;
                s0 += e0 + e1;
                s1 += e2 + e3;
                *(__half2*)(Ph + (size_t)row * ldc + col)       = __floats2half2_rn(e0, e1);
                *(__half2*)(Ph + (size_t)(row + 8) * ldc + col) = __floats2half2_rn(e2, e3);
            } else {
                float* C = (float*)C0 + (size_t)z * sCz;
                const float r0 = 1.f / rsum[z * S_ + row];
                const float r1 = 1.f / rsum[z * S_ + row + 8];
                *(float2*)(C + (size_t)row * ldc + col) =
                    make_float2(c[0] * r0, c[1] * r0);
                *(float2*)(C + (size_t)(row + 8) * ldc + col) =
                    make_float2(c[2] * r1, c[3] * r1);
            }
        }
        if (MODE == 2) {
            // reduce across the quad (tg lanes share the same rows)
            s0 += __shfl_xor_sync(0xffffffffu, s0, 1);
            s0 += __shfl_xor_sync(0xffffffffu, s0, 2);
            s1 += __shfl_xor_sync(0xffffffffu, s1, 1);
            s1 += __shfl_xor_sync(0xffffffffu, s1, 2);
            if (tg == 0) {
                const int row = m0 + wm * 64 + mt * 16 + g;
                atomicAdd(&rsum[z * S_ + row], s0);
                atomicAdd(&rsum[z * S_ + row + 8], s1);
            }
        }
    }
}

// ---------------------------------------------------------------------------
// fp32 -> fp16 conversion (single src)
// ---------------------------------------------------------------------------
__global__ __launch_bounds__(256) void cvt_h(
    const float* __restrict__ in, __half* __restrict__ out)
{
    const size_t i = ((size_t)blockIdx.x * 256 + threadIdx.x) * 4;
    float4 v = *(const float4*)(in + i);
    *(__half2*)(out + i)     = __floats2half2_rn(v.x, v.y);
    *(__half2*)(out + i + 2) = __floats2half2_rn(v.z, v.w);
}

// fp32 -> fp16 conversion for the 3 weight matrices (z-indexed)
__global__ __launch_bounds__(256) void cvt_w(
    const float* __restrict__ w0, const float* __restrict__ w1,
    const float* __restrict__ w2, __half* __restrict__ out)
{
    const int z = blockIdx.y;
    const float* in = (z == 0) ? w0 : ((z == 1) ? w1 : w2);
    const size_t i = ((size_t)blockIdx.x * 256 + threadIdx.x) * 4;
    float4 v = *(const float4*)(in + i);
    __half* o = out + (size_t)z * H_ * D_;
    *(__half2*)(o + i)     = __floats2half2_rn(v.x, v.y);
    *(__half2*)(o + i + 2) = __floats2half2_rn(v.z, v.w);
}

// ---------------------------------------------------------------------------
// Launch pipeline: two symmetric batch-half pipelines on two streams.
// Each pipeline's drain/ramp at every kernel boundary is filled by the
// other pipeline's steady-state work. Fork-join via events (capture-legal).
// ---------------------------------------------------------------------------
extern "C" void kernel_launch(void* const* d_in, const int* in_sizes, int n_in,
                              void* d_out, int out_size)
{
    (void)in_sizes; (void)n_in; (void)out_size;
    const float* x  = (const float*)d_in[0];
    const float* Wq = (const float*)d_in[1];
    const float* bq = (const float*)d_in[2];
    const float* Wk = (const float*)d_in[3];
    const float* bk = (const float*)d_in[4];
    const float* Wv = (const float*)d_in[5];
    const float* bv = (const float*)d_in[6];
    float* out = (float*)d_out;

    __half *xh, *wh, *qkv, *vth, *ph;
    float* rsum;
    cudaGetSymbolAddress((void**)&xh,   g_xh);
    cudaGetSymbolAddress((void**)&wh,   g_wh);
    cudaGetSymbolAddress((void**)&qkv,  g_qkv);
    cudaGetSymbolAddress((void**)&vth,  g_vth);
    cudaGetSymbolAddress((void**)&ph,   g_ph);
    cudaGetSymbolAddress((void**)&rsum, g_rsum);

    const __half* qh = qkv;
    const __half* kh = qkv + (size_t)M_ * H_;

    cudaFuncSetAttribute(gemm_h<0>, cudaFuncAttributeMaxDynamicSharedMemorySize, SMEM_BYTES);
    cudaFuncSetAttribute(gemm_h<2>, cudaFuncAttributeMaxDynamicSharedMemorySize, SMEM_BYTES);
    cudaFuncSetAttribute(gemm_h<3>, cudaFuncAttributeMaxDynamicSharedMemorySize, SMEM_BYTES);

    const dim3 blk(256);
    const int  MH = M_ / 2;               // 8192 rows per half
    const long sQK = (long)S_ * H_;       // q/k batch stride
    const long sP  = (long)S_ * S_;       // p batch stride

    // 0) convert operands to fp16; zero the row-sum accumulator (stream 0)
    cvt_h<<<M_ * D_ / 1024, blk>>>(x, xh);
    cvt_w<<<dim3(H_ * D_ / 1024, 3), blk>>>(Wq, Wk, Wv, wh);
    cudaMemsetAsync(rsum, 0, M_ * sizeof(float));
    cudaEventRecord(g_evCVT, 0);
    cudaStreamWaitEvent(g_s1, g_evCVT, 0);

    // ---- pipeline A (batches 0..3) on stream 0 ----
    const dim3 gqH(H_ / BN, MH / BM, 3);  // 1536 CTAs, z-packed
    gemm_h<0><<<gqH, blk, SMEM_BYTES>>>(xh, wh, bq, bk, bv, qkv, vth, nullptr,
                                        D_, D_, D_, H_,
                                        0, (long)H_ * D_, (long)M_ * H_, 1.f);

    const dim3 gsH(136, 1, 4);
    gemm_h<2><<<gsH, blk, SMEM_BYTES>>>(qh, kh, nullptr, nullptr, nullptr, ph,
                                        nullptr, rsum,
                                        H_, H_, H_, S_,
                                        sQK, sQK, sP, 0.03125f);

    const dim3 gpH(H_ / BN, S_ / BM, 4);
    gemm_h<3><<<gpH, blk, SMEM_BYTES>>>(ph, vth, nullptr, nullptr, nullptr, out,
                                        nullptr, rsum,
                                        S_, S_, M_, H_,
                                        sP, (long)S_, (long)S_ * H_, 1.f);

    // ---- pipeline B (batches 4..7) on stream g_s1 ----
    gemm_h<0><<<gqH, blk, SMEM_BYTES, g_s1>>>(
        xh + (size_t)MH * D_, wh, bq, bk, bv,
        qkv + (size_t)MH * H_, vth + MH, nullptr,
        D_, D_, D_, H_,
        0, (long)H_ * D_, (long)M_ * H_, 1.f);

    gemm_h<2><<<gsH, blk, SMEM_BYTES, g_s1>>>(
        qh + 4 * (size_t)sQK, kh + 4 * (size_t)sQK,
        nullptr, nullptr, nullptr, ph + 4 * (size_t)sP,
        nullptr, rsum + 4 * S_,
        H_, H_, H_, S_,
        sQK, sQK, sP, 0.03125f);

    gemm_h<3><<<gpH, blk, SMEM_BYTES, g_s1>>>(
        ph + 4 * (size_t)sP, vth + 4 * (size_t)S_,
        nullptr, nullptr, nullptr, out + 4 * (size_t)S_ * H_,
        nullptr, rsum + 4 * S_,
        S_, S_, M_, H_,
        sP, (long)S_, (long)S_ * H_, 1.f);

    // join pipeline B back into stream 0
    cudaEventRecord(g_evB, g_s1);
    cudaStreamWaitEvent(0, g_evB, 0);
}